// round 16
// baseline (speedup 1.0000x reference)
#include <cuda_runtime.h>
#include <cuda_fp16.h>
#include <math.h>
#include <stdint.h>

// Problem constants
#define NSEQ 256
#define LRES 384
#define DM   256
#define DP   128
#define NH   8
#define DHD  32
#define HD   256           // NH*DHD
#define NLROWS (NSEQ*LRES) // 98304
#define EPS 1e-5f
#define NWIDE 1024         // 4 fused projection outputs: Q|K|V|G

// -------- scratch (device globals) --------
__device__ __half  g_m[NLROWS * DM];        // LN(msa), fp16
__device__ float   g_qsw[LRES * HD];        // q_sw (scaled), fp32
__device__ __half  g_qw[NLROWS * HD];       // (m@Wq) * seq_weight, fp16
__device__ __half  g_k[NLROWS * HD];        // m@Wk * scale, fp16
__device__ __half  g_v[NLROWS * HD];        // m@Wv, fp16 [n,j,h,d]
__device__ __half  g_gate[NLROWS * HD];     // sigmoid(m@Wg+bg), fp16
__device__ __half  g_aog[NLROWS * HD];      // (attn@v)*gate, fp16
__device__ float   g_sw[NLROWS * NH];       // seq weights
__device__ float   g_logits[NH * LRES * LRES];
__device__ __half  g_attn[NH * LRES * LRES]; // fp16
__device__ __half  g_wpackT[NWIDE * DM];     // packed fp16 [n][k] (K-major!)
__device__ __half  g_w2T[2 * DM * DM];       // fp16 K-major: qSW^T, O^T

// ---- helpers ----
__device__ __forceinline__ uint32_t f2h2(float a, float b) {
    __half2 h = __floats2half2_rn(a, b);
    return *(uint32_t*)&h;
}
__device__ __forceinline__ void mma_f16(float* c,
    uint32_t a0, uint32_t a1, uint32_t a2, uint32_t a3,
    uint32_t b0, uint32_t b1)
{
    asm volatile(
        "mma.sync.aligned.m16n8k16.row.col.f32.f16.f16.f32 "
        "{%0,%1,%2,%3},{%4,%5,%6,%7},{%8,%9},{%0,%1,%2,%3};"
        : "+f"(c[0]), "+f"(c[1]), "+f"(c[2]), "+f"(c[3])
        : "r"(a0), "r"(a1), "r"(a2), "r"(a3), "r"(b0), "r"(b1));
}
__device__ __forceinline__ void cp16(void* s, const void* g) {
    uint32_t sa = (uint32_t)__cvta_generic_to_shared(s);
    asm volatile("cp.async.cg.shared.global [%0], [%1], 16;" :: "r"(sa), "l"(g));
}
__device__ __forceinline__ void ldsm_x4(uint32_t& r0, uint32_t& r1,
                                        uint32_t& r2, uint32_t& r3, const void* p)
{
    uint32_t a = (uint32_t)__cvta_generic_to_shared(p);
    asm volatile("ldmatrix.sync.aligned.m8n8.x4.shared.b16 {%0,%1,%2,%3}, [%4];"
        : "=r"(r0), "=r"(r1), "=r"(r2), "=r"(r3) : "r"(a));
}
__device__ __forceinline__ void ldsm_x4t(uint32_t& r0, uint32_t& r1,
                                         uint32_t& r2, uint32_t& r3, const void* p)
{
    uint32_t a = (uint32_t)__cvta_generic_to_shared(p);
    asm volatile("ldmatrix.sync.aligned.m8n8.x4.trans.shared.b16 {%0,%1,%2,%3}, [%4];"
        : "=r"(r0), "=r"(r1), "=r"(r2), "=r"(r3) : "r"(a));
}
#define CP_COMMIT() asm volatile("cp.async.commit_group;")
#define CP_WAIT(n)  asm volatile("cp.async.wait_group %0;" :: "n"(n))

// =========================================================================
// K0: all weight conversions in one kernel.
// idx < 262144: wpackT [Q|K|V|G] K-major. idx >= : w2T (qSW^T, O^T).
// =========================================================================
__global__ void __launch_bounds__(256) cvtall_kernel(
    const float* wq, const float* wk, const float* wv, const float* wg,
    const float* wqsw, const float* wo, __half* wpackT, __half* w2T)
{
    const int idx = blockIdx.x * 256 + threadIdx.x;   // < 393216
    if (idx < NWIDE * DM) {
        const int c = idx >> 8, k = idx & 255;
        const int seg = c >> 8, cc = c & 255;
        const float* src;
        switch (seg) {
            case 0: src = wq; break; case 1: src = wk; break;
            case 2: src = wv; break; default: src = wg; break;
        }
        wpackT[idx] = __float2half(src[k * DM + cc]);
    } else {
        const int r = idx - NWIDE * DM;               // < 131072
        const int m = r >> 16;
        const int e = r & 65535;
        const int n = e >> 8, k = e & 255;
        const float* src = (m == 0) ? wqsw : wo;
        w2T[r] = __float2half(src[k * DM + n]);
    }
}

// =========================================================================
// K1: LayerNorm, warp-per-row (D=256), 8 rows/block, writes fp16.
// =========================================================================
__global__ void __launch_bounds__(256) ln_msa_kernel(
    const float* __restrict__ x, const float* __restrict__ g,
    const float* __restrict__ b, __half* __restrict__ out)
{
    const int w = threadIdx.x >> 5, lane = threadIdx.x & 31;
    const size_t row = (size_t)blockIdx.x * 8 + w;
    const float* xr = x + row * DM;
    float4 v0 = *(const float4*)(xr + lane * 4);
    float4 v1 = *(const float4*)(xr + 128 + lane * 4);
    float s  = v0.x + v0.y + v0.z + v0.w + v1.x + v1.y + v1.z + v1.w;
    float s2 = v0.x*v0.x + v0.y*v0.y + v0.z*v0.z + v0.w*v0.w
             + v1.x*v1.x + v1.y*v1.y + v1.z*v1.z + v1.w*v1.w;
    #pragma unroll
    for (int o = 16; o; o >>= 1) {
        s  += __shfl_xor_sync(0xffffffffu, s,  o);
        s2 += __shfl_xor_sync(0xffffffffu, s2, o);
    }
    const float mu   = s * (1.f / DM);
    const float rstd = rsqrtf(s2 * (1.f / DM) - mu * mu + EPS);
    float4 g0 = *(const float4*)(g + lane * 4);
    float4 g1 = *(const float4*)(g + 128 + lane * 4);
    float4 b0 = *(const float4*)(b + lane * 4);
    float4 b1 = *(const float4*)(b + 128 + lane * 4);
    uint2 o0, o1;
    o0.x = f2h2((v0.x - mu)*rstd*g0.x + b0.x, (v0.y - mu)*rstd*g0.y + b0.y);
    o0.y = f2h2((v0.z - mu)*rstd*g0.z + b0.z, (v0.w - mu)*rstd*g0.w + b0.w);
    o1.x = f2h2((v1.x - mu)*rstd*g1.x + b1.x, (v1.y - mu)*rstd*g1.y + b1.y);
    o1.y = f2h2((v1.z - mu)*rstd*g1.z + b1.z, (v1.w - mu)*rstd*g1.w + b1.w);
    *(uint2*)(out + row * DM + lane * 4)       = o0;
    *(uint2*)(out + row * DM + 128 + lane * 4) = o1;
}

// =========================================================================
// W1: fp16 GEMM + ldmatrix. Block 128(M) x 64(N), BK=32, 3-stage, 1 sync/iter.
// MODE 0: fused 4-segment epilogue [qw=q*sw | k*scale | v | sigmoid gate], fp16.
// MODE 1: plain fp32 out (+bias0)*scale.
// =========================================================================
#define WG_LOAD(stg, k0) do {                                                 \
    _Pragma("unroll")                                                         \
    for (int s_ = 0; s_ < 2; s_++) {                                          \
        const int r_ = (tid >> 2) + 64 * s_;                                  \
        const int c_ = (tid & 3) * 8;                                         \
        cp16(&As[stg][r_][c_], A + (size_t)(m0 + r_) * K + (k0) + c_);        \
    }                                                                         \
    {                                                                         \
        const int r_ = tid >> 2;                                              \
        const int c_ = (tid & 3) * 8;                                         \
        cp16(&Bs[stg][r_][c_], B + (size_t)(n0 + r_) * K + (k0) + c_);        \
    }                                                                         \
    CP_COMMIT();                                                              \
} while (0)

template<int MODE>
__global__ void __launch_bounds__(256, 3) wgemm_kernel(
    const __half* __restrict__ A, const __half* __restrict__ B,
    int M, int K, int Nld,
    __half* __restrict__ qwf, __half* __restrict__ ktf,
    __half* __restrict__ vtf, __half* __restrict__ gatef,
    const float* __restrict__ swp,
    const float* __restrict__ bias0, const float* __restrict__ bias1,
    float scaleArg, float* __restrict__ C)
{
    __shared__ __half As[3][128][40];
    __shared__ __half Bs[3][64][40];
    const int tid = threadIdx.x;
    const int n0 = blockIdx.x * 64;
    const int m0 = blockIdx.y * 128;
    const int lane = tid & 31, w = tid >> 5;
    const int wm = w >> 1, wn = w & 1;
    const int gid = lane >> 2, tig = lane & 3;
    const int lrow = lane & 7, lgrp = lane >> 3;
    const int arow = wm * 32 + lrow + ((lgrp & 1) ? 8 : 0);
    const int acol = (lgrp & 2) ? 8 : 0;
    const int brow = wn * 32 + lrow + ((lgrp >> 1) ? 8 : 0);
    const int bcol = (lgrp & 1) ? 8 : 0;
    float acc[2][4][4] = {};

    const int T = K >> 5;   // BK=32 -> 8 iters
    WG_LOAD(0, 0);
    WG_LOAD(1, 32);
    int st = 0, ld = 2;
    for (int t = 0; t < T; t++) {
        if (t + 1 < T) { CP_WAIT(1); } else { CP_WAIT(0); }
        __syncthreads();
        if (t + 2 < T) {
            WG_LOAD(ld, (t + 2) << 5);
            ld = (ld == 2) ? 0 : ld + 1;
        }
        #pragma unroll
        for (int ks = 0; ks < 2; ks++) {
            const int kb = ks * 16;
            uint32_t a[2][4], bfr[4][2];
            #pragma unroll
            for (int mt = 0; mt < 2; mt++)
                ldsm_x4(a[mt][0], a[mt][1], a[mt][2], a[mt][3],
                        &As[st][arow + mt * 16][kb + acol]);
            #pragma unroll
            for (int p = 0; p < 2; p++)
                ldsm_x4(bfr[2*p][0], bfr[2*p][1], bfr[2*p+1][0], bfr[2*p+1][1],
                        &Bs[st][brow + p * 16][kb + bcol]);
            #pragma unroll
            for (int mt = 0; mt < 2; mt++)
                #pragma unroll
                for (int nt = 0; nt < 4; nt++)
                    mma_f16(acc[mt][nt], a[mt][0], a[mt][1], a[mt][2], a[mt][3],
                            bfr[nt][0], bfr[nt][1]);
        }
        st = (st == 2) ? 0 : st + 1;
    }
    // epilogue
    const int seg = (MODE == 0) ? (blockIdx.x >> 2) : 0;
    const int hh = ((n0 & 255) + wn * 32) >> 5;   // head index (MODE 0)
    #pragma unroll
    for (int mt = 0; mt < 2; mt++) {
        const int r0 = m0 + wm * 32 + mt * 16 + gid;
        #pragma unroll
        for (int nt = 0; nt < 4; nt++) {
            const int col = n0 + wn * 32 + nt * 8 + 2 * tig;
            float v00 = acc[mt][nt][0], v01 = acc[mt][nt][1];
            float v10 = acc[mt][nt][2], v11 = acc[mt][nt][3];
            if (MODE == 0) {
                const int cc = col & 255;
                const size_t p0 = (size_t)r0 * HD + cc;
                const size_t p1 = (size_t)(r0 + 8) * HD + cc;
                switch (seg) {
                    case 0: {  // qw = q * seq_weight -> fp16
                        const float s0 = swp[(size_t)r0 * NH + hh];
                        const float s1 = swp[(size_t)(r0 + 8) * NH + hh];
                        *(uint32_t*)(qwf + p0) = f2h2(v00 * s0, v01 * s0);
                        *(uint32_t*)(qwf + p1) = f2h2(v10 * s1, v11 * s1);
                        break;
                    }
                    case 1: {  // k * scale -> fp16
                        *(uint32_t*)(ktf + p0) = f2h2(v00 * scaleArg, v01 * scaleArg);
                        *(uint32_t*)(ktf + p1) = f2h2(v10 * scaleArg, v11 * scaleArg);
                        break;
                    }
                    case 2: {  // v -> fp16
                        *(uint32_t*)(vtf + p0) = f2h2(v00, v01);
                        *(uint32_t*)(vtf + p1) = f2h2(v10, v11);
                        break;
                    }
                    default: { // gate = sigmoid(acc + bg) -> fp16
                        const float b0 = bias1[cc], b1 = bias1[cc + 1];
                        *(uint32_t*)(gatef + p0) = f2h2(1.f/(1.f+expf(-(v00+b0))),
                                                        1.f/(1.f+expf(-(v01+b1))));
                        *(uint32_t*)(gatef + p1) = f2h2(1.f/(1.f+expf(-(v10+b0))),
                                                        1.f/(1.f+expf(-(v11+b1))));
                        break;
                    }
                }
            } else {
                const float b0 = bias0 ? bias0[col] : 0.f;
                const float b1 = bias0 ? bias0[col + 1] : 0.f;
                *(float2*)(C + (size_t)r0 * Nld + col) =
                    make_float2((v00 + b0) * scaleArg, (v01 + b1) * scaleArg);
                *(float2*)(C + (size_t)(r0 + 8) * Nld + col) =
                    make_float2((v10 + b0) * scaleArg, (v11 + b1) * scaleArg);
            }
        }
    }
}
#undef WG_LOAD

// =========================================================================
// K3: fused t + seqw softmax. grid (LRES), 256 thr.
// Phase A: thread k computes t[h][k] = dot32(Wk_sw[k, h*32:], qsw[i, h*32:]) -> smem fp16.
// Phase B: thread n: dot[h] = m[n,i,:] . t[h,:]; softmax over n; write sw.
// =========================================================================
__global__ void __launch_bounds__(256) seqw2_kernel(
    const float* __restrict__ qsw, const float* __restrict__ Wk_sw,
    const __half* __restrict__ m, float* __restrict__ sw)
{
    const int i = blockIdx.x;
    const int n = threadIdx.x;
    __shared__ __align__(16) float qs[HD];        // 1KB
    __shared__ __align__(16) __half tk[NH][DM];   // 4KB
    __shared__ float red[8][NH];

    qs[n] = qsw[(size_t)i * HD + n];
    __syncthreads();

    // Phase A: k = n
    {
        const float* wr = Wk_sw + (size_t)n * HD;
        #pragma unroll
        for (int h = 0; h < NH; h++) {
            float acc = 0.f;
            #pragma unroll
            for (int c = 0; c < 8; c++) {
                float4 v = *(const float4*)(wr + h * DHD + 4 * c);
                acc += v.x * qs[h*DHD + 4*c]   + v.y * qs[h*DHD + 4*c+1]
                     + v.z * qs[h*DHD + 4*c+2] + v.w * qs[h*DHD + 4*c+3];
            }
            tk[h][n] = __float2half(acc);
        }
    }
    __syncthreads();

    // Phase B
    const __half* mp = m + ((size_t)n * LRES + i) * DM;
    float dot[NH] = {};
    #pragma unroll 4
    for (int c = 0; c < 32; c++) {
        uint4 mv = *(const uint4*)(mp + 8 * c);
        const __half2* mh = (const __half2*)&mv;
        #pragma unroll
        for (int x = 0; x < 4; x++) {
            const float2 mf = __half22float2(mh[x]);
            const int k = 8 * c + 2 * x;
            #pragma unroll
            for (int h = 0; h < NH; h++) {
                const float2 tf = __half22float2(*(const __half2*)&tk[h][k]);
                dot[h] += mf.x * tf.x + mf.y * tf.y;
            }
        }
    }
    const int w = n >> 5, lane = n & 31;
    float mx[NH];
    #pragma unroll
    for (int h = 0; h < NH; h++) {
        float v = dot[h];
        #pragma unroll
        for (int o = 16; o; o >>= 1) v = fmaxf(v, __shfl_xor_sync(0xffffffffu, v, o));
        if (!lane) red[w][h] = v;
    }
    __syncthreads();
    #pragma unroll
    for (int h = 0; h < NH; h++) {
        float v = red[0][h];
        #pragma unroll
        for (int x = 1; x < 8; x++) v = fmaxf(v, red[x][h]);
        mx[h] = v;
    }
    __syncthreads();
    float e[NH];
    #pragma unroll
    for (int h = 0; h < NH; h++) {
        e[h] = expf(dot[h] - mx[h]);
        float v = e[h];
        #pragma unroll
        for (int o = 16; o; o >>= 1) v += __shfl_xor_sync(0xffffffffu, v, o);
        if (!lane) red[w][h] = v;
    }
    __syncthreads();
    float out[NH];
    #pragma unroll
    for (int h = 0; h < NH; h++) {
        float S = red[0][h];
        #pragma unroll
        for (int x = 1; x < 8; x++) S += red[x][h];
        out[h] = e[h] / S;
    }
    float* swp = sw + ((size_t)n * LRES + i) * NH;
    *(float4*)(swp)     = make_float4(out[0], out[1], out[2], out[3]);
    *(float4*)(swp + 4) = make_float4(out[4], out[5], out[6], out[7]);
}

// =========================================================================
// T2: logits (fp16 mma + ldmatrix). Block 64x64, BK=64 halves, 3-stage.
// grid (6,6,8).
// =========================================================================
#define LG_LOAD(stg, np) do {                                                      \
    const int nb_ = (np) * 2;                                                      \
    _Pragma("unroll")                                                              \
    for (int s_ = 0; s_ < 2; s_++) {                                               \
        const int r_ = (tid >> 3) + 32 * s_;                                       \
        const int col_ = (tid & 7) * 8;                                            \
        const int n_ = nb_ + (col_ >> 5);                                          \
        const int d_ = col_ & 31;                                                  \
        cp16(&As[stg][r_][col_], qw + ((size_t)n_ * LRES + i0 + r_) * HD + h * DHD + d_); \
        cp16(&Bs[stg][r_][col_], kk + ((size_t)n_ * LRES + j0 + r_) * HD + h * DHD + d_); \
    }                                                                              \
    CP_COMMIT();                                                                   \
} while (0)

__global__ void __launch_bounds__(256, 2) logits_tc_kernel(
    const __half* __restrict__ qw, const __half* __restrict__ kk,
    float* __restrict__ out)
{
    extern __shared__ __half dynh[];
    __half (*As)[64][72] = (__half (*)[64][72])dynh;
    __half (*Bs)[64][72] = (__half (*)[64][72])(dynh + 3 * 64 * 72);
    const int tid = threadIdx.x;
    const int i0 = blockIdx.x * 64;
    const int j0 = blockIdx.y * 64;
    const int h  = blockIdx.z;
    const int lane = tid & 31, w = tid >> 5;
    const int wm = w >> 1, wn = w & 1;
    const int gid = lane >> 2, tig = lane & 3;
    const int lrow = lane & 7, lgrp = lane >> 3;
    const int arow = wm * 16 + lrow + ((lgrp & 1) ? 8 : 0);
    const int acol = (lgrp & 2) ? 8 : 0;
    const int brow = wn * 32 + lrow + ((lgrp >> 1) ? 8 : 0);
    const int bcol = (lgrp & 1) ? 8 : 0;
    float acc[4][4] = {};

    const int T = NSEQ / 2;   // 128
    LG_LOAD(0, 0);
    LG_LOAD(1, 1);
    int st = 0, ld = 2;
    for (int t = 0; t < T; t++) {
        if (t + 1 < T) { CP_WAIT(1); } else { CP_WAIT(0); }
        __syncthreads();
        if (t + 2 < T) {
            LG_LOAD(ld, t + 2);
            ld = (ld == 2) ? 0 : ld + 1;
        }
        #pragma unroll
        for (int ks = 0; ks < 4; ks++) {
            const int kb = ks * 16;
            uint32_t a[4], bfr[4][2];
            ldsm_x4(a[0], a[1], a[2], a[3], &As[st][arow][kb + acol]);
            #pragma unroll
            for (int p = 0; p < 2; p++)
                ldsm_x4(bfr[2*p][0], bfr[2*p][1], bfr[2*p+1][0], bfr[2*p+1][1],
                        &Bs[st][brow + p * 16][kb + bcol]);
            #pragma unroll
            for (int nt = 0; nt < 4; nt++)
                mma_f16(acc[nt], a[0], a[1], a[2], a[3], bfr[nt][0], bfr[nt][1]);
        }
        st = (st == 2) ? 0 : st + 1;
    }
    const size_t ob = (size_t)h * LRES * LRES;
    const int r0 = i0 + wm * 16 + gid;
    #pragma unroll
    for (int nt = 0; nt < 4; nt++) {
        const int col = j0 + wn * 32 + nt * 8 + 2 * tig;
        *(float2*)(out + ob + (size_t)r0 * LRES + col)     = make_float2(acc[nt][0], acc[nt][1]);
        *(float2*)(out + ob + (size_t)(r0+8) * LRES + col) = make_float2(acc[nt][2], acc[nt][3]);
    }
}
#undef LG_LOAD

// =========================================================================
// K6: fused pair-bias + softmax -> fp16 attn. One block per i, 512 thr.
// Phase 1: 16 warps, warp-per-j stride 16 (24 iters).
// Phase 2: head h = w>>1, part p = w&1, each warp handles 192 j.
// =========================================================================
__global__ void __launch_bounds__(512) pairsoftmax_kernel(
    const float* __restrict__ pair, const float* __restrict__ g,
    const float* __restrict__ b, const float* __restrict__ Wb,
    const float* __restrict__ logits, __half* __restrict__ attn)
{
    __shared__ float bias_s[LRES][NH + 1];
    __shared__ float redm[NH][2], reds[NH][2];
    const int i = blockIdx.x;
    const int w = threadIdx.x >> 5, lane = threadIdx.x & 31;

    for (int j = w; j < LRES; j += 16) {
        const size_t p = (size_t)i * LRES + j;
        float4 v = *(const float4*)(pair + p * DP + lane * 4);
        float s  = v.x + v.y + v.z + v.w;
        float s2 = v.x*v.x + v.y*v.y + v.z*v.z + v.w*v.w;
        #pragma unroll
        for (int o = 16; o; o >>= 1) {
            s  += __shfl_xor_sync(0xffffffffu, s,  o);
            s2 += __shfl_xor_sync(0xffffffffu, s2, o);
        }
        const float mu   = s * (1.f / DP);
        const float rstd = rsqrtf(s2 * (1.f / DP) - mu * mu + EPS);
        float xv[4] = {v.x, v.y, v.z, v.w};
        float acc[8] = {};
        #pragma unroll
        for (int c = 0; c < 4; c++) {
            const int d = lane * 4 + c;
            const float y = (xv[c] - mu) * rstd * g[d] + b[d];
            const float* wr = Wb + d * NH;
            #pragma unroll
            for (int hh = 0; hh < 8; hh++) acc[hh] = fmaf(y, wr[hh], acc[hh]);
        }
        #pragma unroll
        for (int hh = 0; hh < 8; hh++) {
            float a = acc[hh];
            #pragma unroll
            for (int o = 16; o; o >>= 1) a += __shfl_xor_sync(0xffffffffu, a, o);
            if (lane == hh) bias_s[j][hh] = a;
        }
    }
    __syncthreads();

    // phase 2: head h = w>>1, half p = w&1 (j in [p*192, p*192+192))
    const int h = w >> 1, p = w & 1;
    const int jb = p * 192;
    const size_t base = ((size_t)h * LRES + i) * LRES;
    float x[6];
    #pragma unroll
    for (int r = 0; r < 3; r++) {
        const int j = jb + 2 * lane + 64 * r;
        float2 lg = *(const float2*)(logits + base + j);
        x[2*r]   = lg.x + bias_s[j][h];
        x[2*r+1] = lg.y + bias_s[j + 1][h];
    }
    float mx = x[0];
    #pragma unroll
    for (int r = 1; r < 6; r++) mx = fmaxf(mx, x[r]);
    #pragma unroll
    for (int o = 16; o; o >>= 1) mx = fmaxf(mx, __shfl_xor_sync(0xffffffffu, mx, o));
    if (!lane) redm[h][p] = mx;
    __syncthreads();
    mx = fmaxf(redm[h][0], redm[h][1]);
    float e[6], sum = 0.f;
    #pragma unroll
    for (int r = 0; r < 6; r++) { e[r] = expf(x[r] - mx); sum += e[r]; }
    #pragma unroll
    for (int o = 16; o; o >>= 1) sum += __shfl_xor_sync(0xffffffffu, sum, o);
    if (!lane) reds[h][p] = sum;
    __syncthreads();
    const float inv = 1.f / (reds[h][0] + reds[h][1]);
    #pragma unroll
    for (int r = 0; r < 3; r++) {
        *(uint32_t*)(attn + base + jb + 2 * lane + 64 * r) =
            f2h2(e[2*r] * inv, e[2*r+1] * inv);
    }
}

// =========================================================================
// T3: aog = fp16(gate * (attn @ v)). Block 128(i) x 64(nd), BK=32(j).
// B = v[n,j,h,d] loaded as [j][nd] smem tiles, ldmatrix.trans fragments.
// grid (3, 128, 8).
// =========================================================================
#define AO_LOAD(stg, j0) do {                                                       \
    _Pragma("unroll")                                                               \
    for (int s_ = 0; s_ < 2; s_++) {                                                \
        const int r_ = (tid >> 2) + 64 * s_;                                        \
        const int c_ = (tid & 3) * 8;                                               \
        cp16(&As[stg][r_][c_], Ah + (size_t)(i0 + r_) * LRES + (j0) + c_);          \
    }                                                                               \
    {                                                                               \
        const int jj_ = tid >> 3;        /* 0..31 j within tile */                  \
        const int cc_ = (tid & 7) * 8;   /* 0..56 nd chunk */                       \
        const int nB_ = (blockIdx.y << 1) + (cc_ >> 5);                             \
        const int dB_ = cc_ & 31;                                                   \
        cp16(&Bs[stg][jj_][cc_],                                                    \
             vv + ((size_t)nB_ * LRES + (j0) + jj_) * HD + h * DHD + dB_);          \
    }                                                                               \
    CP_COMMIT();                                                                    \
} while (0)

__global__ void __launch_bounds__(256, 2) attnout_tc_kernel(
    const __half* __restrict__ attn, const __half* __restrict__ vv,
    const __half* __restrict__ gate, __half* __restrict__ aog)
{
    __shared__ __half As[3][128][40];
    __shared__ __half Bs[3][32][72];   // [j][nd]
    const int tid = threadIdx.x;
    const int i0 = blockIdx.x * 128;
    const int h  = blockIdx.z;
    const int lane = tid & 31, w = tid >> 5;
    const int wm = w >> 1, wn = w & 1;
    const int gid = lane >> 2, tig = lane & 3;
    const int lrow = lane & 7, lgrp = lane >> 3;
    const int arow = wm * 32 + lrow + ((lgrp & 1) ? 8 : 0);
    const int acol = (lgrp & 2) ? 8 : 0;
    const int btrow = lrow + ((lgrp & 1) ? 8 : 0);
    const int btcol = wn * 32 + ((lgrp >> 1) ? 8 : 0);
    const __half* Ah = attn + (size_t)h * LRES * LRES;
    float acc[2][4][4] = {};

    const int T = LRES / 32;  // 12
    AO_LOAD(0, 0);
    AO_LOAD(1, 32);
    int st = 0, ld = 2;
    for (int t = 0; t < T; t++) {
        if (t + 1 < T) { CP_WAIT(1); } else { CP_WAIT(0); }
        __syncthreads();
        if (t + 2 < T) {
            AO_LOAD(ld, (t + 2) * 32);
            ld = (ld == 2) ? 0 : ld + 1;
        }
        #pragma unroll
        for (int ks = 0; ks < 2; ks++) {
            const int kb = ks * 16;
            uint32_t a[2][4], bfr[4][2];
            #pragma unroll
            for (int mt = 0; mt < 2; mt++)
                ldsm_x4(a[mt][0], a[mt][1], a[mt][2], a[mt][3],
                        &As[st][arow + mt * 16][kb + acol]);
            #pragma unroll
            for (int p = 0; p < 2; p++)
                ldsm_x4t(bfr[2*p][0], bfr[2*p][1], bfr[2*p+1][0], bfr[2*p+1][1],
                         &Bs[st][kb + btrow][btcol + p * 16]);
            #pragma unroll
            for (int mt = 0; mt < 2; mt++)
                #pragma unroll
                for (int nt = 0; nt < 4; nt++)
                    mma_f16(acc[mt][nt], a[mt][0], a[mt][1], a[mt][2], a[mt][3],
                            bfr[nt][0], bfr[nt][1]);
        }
        st = (st == 2) ? 0 : st + 1;
    }
    #pragma unroll
    for (int mt = 0; mt < 2; mt++) {
        const int r0 = i0 + wm * 32 + mt * 16 + gid;
        #pragma unroll
        for (int nt = 0; nt < 4; nt++) {
            const int col = wn * 32 + nt * 8 + 2 * tig;      // nd within 64
            const int nOut = (blockIdx.y << 1) + (col >> 5);
            const int d = col & 31;
            const size_t p0 = ((size_t)nOut * LRES + r0) * HD + h * DHD + d;
            const size_t p1 = ((size_t)nOut * LRES + r0 + 8) * HD + h * DHD + d;
            const float2 gA = __half22float2(*(const __half2*)(gate + p0));
            const float2 gB = __half22float2(*(const __half2*)(gate + p1));
            *(uint32_t*)(aog + p0) = f2h2(acc[mt][nt][0] * gA.x, acc[mt][nt][1] * gA.y);
            *(uint32_t*)(aog + p1) = f2h2(acc[mt][nt][2] * gB.x, acc[mt][nt][3] * gB.y);
        }
    }
}
#undef AO_LOAD

// =========================================================================
// launcher
// =========================================================================
extern "C" void kernel_launch(void* const* d_in, const int* in_sizes, int n_in,
                              void* d_out, int out_size)
{
    const float* msa       = (const float*)d_in[0];
    const float* pair      = (const float*)d_in[1];
    const float* ln_msa_g  = (const float*)d_in[2];
    const float* ln_msa_b  = (const float*)d_in[3];
    const float* ln_pair_g = (const float*)d_in[4];
    const float* ln_pair_b = (const float*)d_in[5];
    const float* Wq_sw     = (const float*)d_in[6];
    const float* bq_sw     = (const float*)d_in[7];
    const float* Wk_sw     = (const float*)d_in[8];
    const float* bk_sw     = (const float*)d_in[9];   // unused: cancels in softmax
    const float* Wq        = (const float*)d_in[10];
    const float* Wk        = (const float*)d_in[11];
    const float* Wv        = (const float*)d_in[12];
    const float* Wb        = (const float*)d_in[13];
    const float* Wg        = (const float*)d_in[14];
    const float* bg        = (const float*)d_in[15];
    const float* Wo        = (const float*)d_in[16];
    const float* bo        = (const float*)d_in[17];
    float* out = (float*)d_out;
    (void)bk_sw;

    __half *m_, *qw_, *k_, *v_, *gate_, *aog_, *attn_, *wpackT_, *w2T_;
    float *qsw_, *sw_, *logits_;
    cudaGetSymbolAddress((void**)&m_,      g_m);
    cudaGetSymbolAddress((void**)&qsw_,    g_qsw);
    cudaGetSymbolAddress((void**)&qw_,     g_qw);
    cudaGetSymbolAddress((void**)&k_,      g_k);
    cudaGetSymbolAddress((void**)&v_,      g_v);
    cudaGetSymbolAddress((void**)&gate_,   g_gate);
    cudaGetSymbolAddress((void**)&aog_,    g_aog);
    cudaGetSymbolAddress((void**)&sw_,     g_sw);
    cudaGetSymbolAddress((void**)&logits_, g_logits);
    cudaGetSymbolAddress((void**)&attn_,   g_attn);
    cudaGetSymbolAddress((void**)&wpackT_, g_wpackT);
    cudaGetSymbolAddress((void**)&w2T_,    g_w2T);

    const float scale = 0.17677669529663687f;  // 1/sqrt(32)
    const __half *WqSWT = w2T_, *WOT = w2T_ + DM * DM;

    const int LG_SMEM = (3 * 64 * 72 * 2) * 2;    // 55296
    cudaFuncSetAttribute((const void*)logits_tc_kernel,
        cudaFuncAttributeMaxDynamicSharedMemorySize, LG_SMEM);

    // preprocessing: all weight conversions + LN
    cvtall_kernel<<<(NWIDE * DM + 2 * DM * DM) / 256, 256>>>(
        Wq, Wk, Wv, Wg, Wq_sw, Wo, wpackT_, w2T_);
    ln_msa_kernel<<<NLROWS / 8, 256>>>(msa, ln_msa_g, ln_msa_b, m_);

    // qsw: (m0 @ Wq_sw + bq_sw) * scale (fp32 out)
    wgemm_kernel<1><<<dim3(HD / 64, LRES / 128), 256>>>(
        m_, WqSWT, LRES, DM, HD,
        nullptr, nullptr, nullptr, nullptr, nullptr, bq_sw, nullptr, scale, qsw_);

    // fused t + seq-weight softmax
    seqw2_kernel<<<LRES, 256>>>(qsw_, Wk_sw, m_, sw_);

    // fused 4-way projection; q segment scaled by sw -> qw directly
    wgemm_kernel<0><<<dim3(NWIDE / 64, NLROWS / 128), 256>>>(
        m_, wpackT_, NLROWS, DM, NWIDE,
        qw_, k_, v_, gate_, sw_, nullptr, bg, scale, nullptr);

    // logits
    logits_tc_kernel<<<dim3(LRES / 64, LRES / 64, NH), 256, LG_SMEM>>>(qw_, k_, logits_);

    // fused pair bias + softmax (fp16 attn), 512 threads
    pairsoftmax_kernel<<<LRES, 512>>>(pair, ln_pair_g, ln_pair_b, Wb, logits_, attn_);

    // attn @ v (gate fused, v read directly via ldmatrix.trans)
    attnout_tc_kernel<<<dim3(LRES / 128, NSEQ / 2, NH), 256>>>(attn_, v_, gate_, aog_);

    // final: aog @ Wo + bo
    wgemm_kernel<1><<<dim3(DM / 64, NLROWS / 128), 256>>>(
        aog_, WOT, NLROWS, DM, DM,
        nullptr, nullptr, nullptr, nullptr, nullptr, bo, nullptr, 1.f, out);
}

// round 17
// speedup vs baseline: 1.0213x; 1.0213x over previous
#include <cuda_runtime.h>
#include <cuda_fp16.h>
#include <math.h>
#include <stdint.h>

// Problem constants
#define NSEQ 256
#define LRES 384
#define DM   256
#define DP   128
#define NH   8
#define DHD  32
#define HD   256           // NH*DHD
#define NLROWS (NSEQ*LRES) // 98304
#define EPS 1e-5f
#define NWIDE 1024         // 4 fused projection outputs: Q|K|V|G

// -------- scratch (device globals) --------
__device__ __half  g_m[NLROWS * DM];        // LN(msa), fp16
__device__ float   g_qsw[LRES * HD];        // q_sw (scaled), fp32
__device__ __half  g_t[LRES * NH * DM];     // t[i,h,:] = Wk_sw_h @ qsw[i,h], fp16
__device__ __half  g_qw[NLROWS * HD];       // (m@Wq) * seq_weight, fp16
__device__ __half  g_k[NLROWS * HD];        // m@Wk * scale, fp16
__device__ __half  g_v[NLROWS * HD];        // m@Wv, fp16 [n,j,h,d]
__device__ __half  g_gate[NLROWS * HD];     // sigmoid(m@Wg+bg), fp16
__device__ __half  g_aog[NLROWS * HD];      // (attn@v)*gate, fp16
__device__ float   g_sw[NLROWS * NH];       // seq weights
__device__ float   g_logits[NH * LRES * LRES];
__device__ __half  g_attn[NH * LRES * LRES]; // fp16
__device__ __half  g_wpackT[NWIDE * DM];     // packed fp16 [n][k] (K-major!)
__device__ __half  g_w2T[2 * DM * DM];       // fp16 K-major: qSW^T, O^T

// ---- helpers ----
__device__ __forceinline__ uint32_t f2h2(float a, float b) {
    __half2 h = __floats2half2_rn(a, b);
    return *(uint32_t*)&h;
}
__device__ __forceinline__ void mma_f16(float* c,
    uint32_t a0, uint32_t a1, uint32_t a2, uint32_t a3,
    uint32_t b0, uint32_t b1)
{
    asm volatile(
        "mma.sync.aligned.m16n8k16.row.col.f32.f16.f16.f32 "
        "{%0,%1,%2,%3},{%4,%5,%6,%7},{%8,%9},{%0,%1,%2,%3};"
        : "+f"(c[0]), "+f"(c[1]), "+f"(c[2]), "+f"(c[3])
        : "r"(a0), "r"(a1), "r"(a2), "r"(a3), "r"(b0), "r"(b1));
}
__device__ __forceinline__ void cp16(void* s, const void* g) {
    uint32_t sa = (uint32_t)__cvta_generic_to_shared(s);
    asm volatile("cp.async.cg.shared.global [%0], [%1], 16;" :: "r"(sa), "l"(g));
}
__device__ __forceinline__ void ldsm_x4(uint32_t& r0, uint32_t& r1,
                                        uint32_t& r2, uint32_t& r3, const void* p)
{
    uint32_t a = (uint32_t)__cvta_generic_to_shared(p);
    asm volatile("ldmatrix.sync.aligned.m8n8.x4.shared.b16 {%0,%1,%2,%3}, [%4];"
        : "=r"(r0), "=r"(r1), "=r"(r2), "=r"(r3) : "r"(a));
}
__device__ __forceinline__ void ldsm_x4t(uint32_t& r0, uint32_t& r1,
                                         uint32_t& r2, uint32_t& r3, const void* p)
{
    uint32_t a = (uint32_t)__cvta_generic_to_shared(p);
    asm volatile("ldmatrix.sync.aligned.m8n8.x4.trans.shared.b16 {%0,%1,%2,%3}, [%4];"
        : "=r"(r0), "=r"(r1), "=r"(r2), "=r"(r3) : "r"(a));
}
#define CP_COMMIT() asm volatile("cp.async.commit_group;")
#define CP_WAIT(n)  asm volatile("cp.async.wait_group %0;" :: "n"(n))

// =========================================================================
// K0a: packed fp16 weight, K-MAJOR: wpackT[c][k], c = [Q|K|V|G] cols.
// =========================================================================
__global__ void __launch_bounds__(256) cvt_pack_kernel(
    const float* w0, const float* w1, const float* w2, const float* w3,
    __half* dst)
{
    const int idx = blockIdx.x * 256 + threadIdx.x;   // < 1024*256
    const int c = idx >> 8, k = idx & 255;
    const int seg = c >> 8, cc = c & 255;
    const float* src;
    switch (seg) {
        case 0: src = w0; break; case 1: src = w1; break;
        case 2: src = w2; break; default: src = w3; break;
    }
    dst[idx] = __float2half(src[k * DM + cc]);
}
__global__ void __launch_bounds__(256) cvt2_kernel(
    const float* w0, const float* w1, __half* dst)
{
    const int m = blockIdx.y;
    const int idx = blockIdx.x * 256 + threadIdx.x;
    const int n = idx >> 8, k = idx & 255;
    const float* src = (m == 0) ? w0 : w1;
    dst[m * (DM * DM) + idx] = __float2half(src[k * DM + n]);
}

// =========================================================================
// K1: LayerNorm, warp-per-row (D=256), 8 rows/block, writes fp16.
// =========================================================================
__global__ void __launch_bounds__(256) ln_msa_kernel(
    const float* __restrict__ x, const float* __restrict__ g,
    const float* __restrict__ b, __half* __restrict__ out)
{
    const int w = threadIdx.x >> 5, lane = threadIdx.x & 31;
    const size_t row = (size_t)blockIdx.x * 8 + w;
    const float* xr = x + row * DM;
    float4 v0 = *(const float4*)(xr + lane * 4);
    float4 v1 = *(const float4*)(xr + 128 + lane * 4);
    float s  = v0.x + v0.y + v0.z + v0.w + v1.x + v1.y + v1.z + v1.w;
    float s2 = v0.x*v0.x + v0.y*v0.y + v0.z*v0.z + v0.w*v0.w
             + v1.x*v1.x + v1.y*v1.y + v1.z*v1.z + v1.w*v1.w;
    #pragma unroll
    for (int o = 16; o; o >>= 1) {
        s  += __shfl_xor_sync(0xffffffffu, s,  o);
        s2 += __shfl_xor_sync(0xffffffffu, s2, o);
    }
    const float mu   = s * (1.f / DM);
    const float rstd = rsqrtf(s2 * (1.f / DM) - mu * mu + EPS);
    float4 g0 = *(const float4*)(g + lane * 4);
    float4 g1 = *(const float4*)(g + 128 + lane * 4);
    float4 b0 = *(const float4*)(b + lane * 4);
    float4 b1 = *(const float4*)(b + 128 + lane * 4);
    uint2 o0, o1;
    o0.x = f2h2((v0.x - mu)*rstd*g0.x + b0.x, (v0.y - mu)*rstd*g0.y + b0.y);
    o0.y = f2h2((v0.z - mu)*rstd*g0.z + b0.z, (v0.w - mu)*rstd*g0.w + b0.w);
    o1.x = f2h2((v1.x - mu)*rstd*g1.x + b1.x, (v1.y - mu)*rstd*g1.y + b1.y);
    o1.y = f2h2((v1.z - mu)*rstd*g1.z + b1.z, (v1.w - mu)*rstd*g1.w + b1.w);
    *(uint2*)(out + row * DM + lane * 4)       = o0;
    *(uint2*)(out + row * DM + 128 + lane * 4) = o1;
}

// =========================================================================
// W1: fp16 GEMM + ldmatrix. Block 128(M) x 64(N), BK=32, 3-stage, 1 sync/iter.
// MODE 0: fused 4-segment epilogue [qw=q*sw | k*scale | v | sigmoid gate], fp16.
// MODE 1: plain fp32 out (+bias0)*scale.
// =========================================================================
#define WG_LOAD(stg, k0) do {                                                 \
    _Pragma("unroll")                                                         \
    for (int s_ = 0; s_ < 2; s_++) {                                          \
        const int r_ = (tid >> 2) + 64 * s_;                                  \
        const int c_ = (tid & 3) * 8;                                         \
        cp16(&As[stg][r_][c_], A + (size_t)(m0 + r_) * K + (k0) + c_);        \
    }                                                                         \
    {                                                                         \
        const int r_ = tid >> 2;                                              \
        const int c_ = (tid & 3) * 8;                                         \
        cp16(&Bs[stg][r_][c_], B + (size_t)(n0 + r_) * K + (k0) + c_);        \
    }                                                                         \
    CP_COMMIT();                                                              \
} while (0)

template<int MODE>
__global__ void __launch_bounds__(256, 3) wgemm_kernel(
    const __half* __restrict__ A, const __half* __restrict__ B,
    int M, int K, int Nld,
    __half* __restrict__ qwf, __half* __restrict__ ktf,
    __half* __restrict__ vtf, __half* __restrict__ gatef,
    const float* __restrict__ swp,
    const float* __restrict__ bias0, const float* __restrict__ bias1,
    float scaleArg, float* __restrict__ C)
{
    __shared__ __half As[3][128][40];
    __shared__ __half Bs[3][64][40];
    const int tid = threadIdx.x;
    const int n0 = blockIdx.x * 64;
    const int m0 = blockIdx.y * 128;
    const int lane = tid & 31, w = tid >> 5;
    const int wm = w >> 1, wn = w & 1;
    const int gid = lane >> 2, tig = lane & 3;
    const int lrow = lane & 7, lgrp = lane >> 3;
    const int arow = wm * 32 + lrow + ((lgrp & 1) ? 8 : 0);
    const int acol = (lgrp & 2) ? 8 : 0;
    const int brow = wn * 32 + lrow + ((lgrp >> 1) ? 8 : 0);
    const int bcol = (lgrp & 1) ? 8 : 0;
    float acc[2][4][4] = {};

    const int T = K >> 5;   // BK=32 -> 8 iters
    WG_LOAD(0, 0);
    WG_LOAD(1, 32);
    int st = 0, ld = 2;
    for (int t = 0; t < T; t++) {
        if (t + 1 < T) { CP_WAIT(1); } else { CP_WAIT(0); }
        __syncthreads();
        if (t + 2 < T) {
            WG_LOAD(ld, (t + 2) << 5);
            ld = (ld == 2) ? 0 : ld + 1;
        }
        #pragma unroll
        for (int ks = 0; ks < 2; ks++) {
            const int kb = ks * 16;
            uint32_t a[2][4], bfr[4][2];
            #pragma unroll
            for (int mt = 0; mt < 2; mt++)
                ldsm_x4(a[mt][0], a[mt][1], a[mt][2], a[mt][3],
                        &As[st][arow + mt * 16][kb + acol]);
            #pragma unroll
            for (int p = 0; p < 2; p++)
                ldsm_x4(bfr[2*p][0], bfr[2*p][1], bfr[2*p+1][0], bfr[2*p+1][1],
                        &Bs[st][brow + p * 16][kb + bcol]);
            #pragma unroll
            for (int mt = 0; mt < 2; mt++)
                #pragma unroll
                for (int nt = 0; nt < 4; nt++)
                    mma_f16(acc[mt][nt], a[mt][0], a[mt][1], a[mt][2], a[mt][3],
                            bfr[nt][0], bfr[nt][1]);
        }
        st = (st == 2) ? 0 : st + 1;
    }
    // epilogue
    const int seg = (MODE == 0) ? (blockIdx.x >> 2) : 0;
    const int hh = ((n0 & 255) + wn * 32) >> 5;   // head index (MODE 0)
    #pragma unroll
    for (int mt = 0; mt < 2; mt++) {
        const int r0 = m0 + wm * 32 + mt * 16 + gid;
        #pragma unroll
        for (int nt = 0; nt < 4; nt++) {
            const int col = n0 + wn * 32 + nt * 8 + 2 * tig;
            float v00 = acc[mt][nt][0], v01 = acc[mt][nt][1];
            float v10 = acc[mt][nt][2], v11 = acc[mt][nt][3];
            if (MODE == 0) {
                const int cc = col & 255;
                const size_t p0 = (size_t)r0 * HD + cc;
                const size_t p1 = (size_t)(r0 + 8) * HD + cc;
                switch (seg) {
                    case 0: {  // qw = q * seq_weight -> fp16
                        const float s0 = swp[(size_t)r0 * NH + hh];
                        const float s1 = swp[(size_t)(r0 + 8) * NH + hh];
                        *(uint32_t*)(qwf + p0) = f2h2(v00 * s0, v01 * s0);
                        *(uint32_t*)(qwf + p1) = f2h2(v10 * s1, v11 * s1);
                        break;
                    }
                    case 1: {  // k * scale -> fp16
                        *(uint32_t*)(ktf + p0) = f2h2(v00 * scaleArg, v01 * scaleArg);
                        *(uint32_t*)(ktf + p1) = f2h2(v10 * scaleArg, v11 * scaleArg);
                        break;
                    }
                    case 2: {  // v -> fp16
                        *(uint32_t*)(vtf + p0) = f2h2(v00, v01);
                        *(uint32_t*)(vtf + p1) = f2h2(v10, v11);
                        break;
                    }
                    default: { // gate = sigmoid(acc + bg) -> fp16
                        const float b0 = bias1[cc], b1 = bias1[cc + 1];
                        *(uint32_t*)(gatef + p0) = f2h2(1.f/(1.f+expf(-(v00+b0))),
                                                        1.f/(1.f+expf(-(v01+b1))));
                        *(uint32_t*)(gatef + p1) = f2h2(1.f/(1.f+expf(-(v10+b0))),
                                                        1.f/(1.f+expf(-(v11+b1))));
                        break;
                    }
                }
            } else {
                const float b0 = bias0 ? bias0[col] : 0.f;
                const float b1 = bias0 ? bias0[col + 1] : 0.f;
                *(float2*)(C + (size_t)r0 * Nld + col) =
                    make_float2((v00 + b0) * scaleArg, (v01 + b1) * scaleArg);
                *(float2*)(C + (size_t)(r0 + 8) * Nld + col) =
                    make_float2((v10 + b0) * scaleArg, (v11 + b1) * scaleArg);
            }
        }
    }
}
#undef WG_LOAD

// =========================================================================
// K2t: t[i,h,k] = sum_d qsw[i,h*32+d] * Wk_sw[k, h*32+d]. grid (LRES, NH).
// =========================================================================
__global__ void __launch_bounds__(256) t_kernel(
    const float* __restrict__ qsw, const float* __restrict__ Wk_sw,
    __half* __restrict__ t)
{
    const int i = blockIdx.x, h = blockIdx.y;
    const int k = threadIdx.x;
    __shared__ float qs[DHD];
    if (k < DHD) qs[k] = qsw[(size_t)i * HD + h * DHD + k];
    __syncthreads();
    const float* wr = Wk_sw + (size_t)k * HD + h * DHD;
    float acc = 0.f;
    #pragma unroll
    for (int c = 0; c < 8; c++) {
        float4 v = *(const float4*)(wr + 4 * c);
        acc += v.x * qs[4*c] + v.y * qs[4*c+1] + v.z * qs[4*c+2] + v.w * qs[4*c+3];
    }
    t[((size_t)i * NH + h) * DM + k] = __float2half(acc);
}

// =========================================================================
// K3: seqw2: sw[n,i,h] = softmax_n( m[n,i,:] . t[i,h,:] ). grid (LRES), 256 thr.
// Vectorized: tk rows read as uint4 LDS.128 broadcasts (8 halves/issue).
// =========================================================================
__global__ void __launch_bounds__(256) seqw2_kernel(
    const __half* __restrict__ m, const __half* __restrict__ t,
    float* __restrict__ sw)
{
    const int i = blockIdx.x;
    const int n = threadIdx.x;
    __shared__ __align__(16) __half tk[NH][DM];   // 4KB
    __shared__ float red[8][NH];
    ((uint4*)tk)[n] = ((const uint4*)(t + (size_t)i * NH * DM))[n];
    __syncthreads();

    const __half* mp = m + ((size_t)n * LRES + i) * DM;
    float dot[NH] = {};
    #pragma unroll 2
    for (int c = 0; c < 32; c++) {            // 32 x uint4 = 256 halves
        uint4 mv = *(const uint4*)(mp + 8 * c);
        const __half2* mh = (const __half2*)&mv;
        #pragma unroll
        for (int h = 0; h < NH; h++) {
            uint4 tv = *(const uint4*)(&tk[h][8 * c]);   // LDS.128 broadcast
            const __half2* th = (const __half2*)&tv;
            #pragma unroll
            for (int x = 0; x < 4; x++) {
                const float2 mf = __half22float2(mh[x]);
                const float2 tf = __half22float2(th[x]);
                dot[h] += mf.x * tf.x + mf.y * tf.y;
            }
        }
    }
    const int w = n >> 5, lane = n & 31;
    float mx[NH];
    #pragma unroll
    for (int h = 0; h < NH; h++) {
        float v = dot[h];
        #pragma unroll
        for (int o = 16; o; o >>= 1) v = fmaxf(v, __shfl_xor_sync(0xffffffffu, v, o));
        if (!lane) red[w][h] = v;
    }
    __syncthreads();
    #pragma unroll
    for (int h = 0; h < NH; h++) {
        float v = red[0][h];
        #pragma unroll
        for (int x = 1; x < 8; x++) v = fmaxf(v, red[x][h]);
        mx[h] = v;
    }
    __syncthreads();
    float e[NH];
    #pragma unroll
    for (int h = 0; h < NH; h++) {
        e[h] = expf(dot[h] - mx[h]);
        float v = e[h];
        #pragma unroll
        for (int o = 16; o; o >>= 1) v += __shfl_xor_sync(0xffffffffu, v, o);
        if (!lane) red[w][h] = v;
    }
    __syncthreads();
    float out[NH];
    #pragma unroll
    for (int h = 0; h < NH; h++) {
        float S = red[0][h];
        #pragma unroll
        for (int x = 1; x < 8; x++) S += red[x][h];
        out[h] = e[h] / S;
    }
    float* swp = sw + ((size_t)n * LRES + i) * NH;
    *(float4*)(swp)     = make_float4(out[0], out[1], out[2], out[3]);
    *(float4*)(swp + 4) = make_float4(out[4], out[5], out[6], out[7]);
}

// =========================================================================
// T2: logits (fp16 mma + ldmatrix). Block 64x64, BK=64 halves, 3-stage.
// grid (6,6,8).
// =========================================================================
#define LG_LOAD(stg, np) do {                                                      \
    const int nb_ = (np) * 2;                                                      \
    _Pragma("unroll")                                                              \
    for (int s_ = 0; s_ < 2; s_++) {                                               \
        const int r_ = (tid >> 3) + 32 * s_;                                       \
        const int col_ = (tid & 7) * 8;                                            \
        const int n_ = nb_ + (col_ >> 5);                                          \
        const int d_ = col_ & 31;                                                  \
        cp16(&As[stg][r_][col_], qw + ((size_t)n_ * LRES + i0 + r_) * HD + h * DHD + d_); \
        cp16(&Bs[stg][r_][col_], kk + ((size_t)n_ * LRES + j0 + r_) * HD + h * DHD + d_); \
    }                                                                              \
    CP_COMMIT();                                                                   \
} while (0)

__global__ void __launch_bounds__(256, 2) logits_tc_kernel(
    const __half* __restrict__ qw, const __half* __restrict__ kk,
    float* __restrict__ out)
{
    extern __shared__ __half dynh[];
    __half (*As)[64][72] = (__half (*)[64][72])dynh;
    __half (*Bs)[64][72] = (__half (*)[64][72])(dynh + 3 * 64 * 72);
    const int tid = threadIdx.x;
    const int i0 = blockIdx.x * 64;
    const int j0 = blockIdx.y * 64;
    const int h  = blockIdx.z;
    const int lane = tid & 31, w = tid >> 5;
    const int wm = w >> 1, wn = w & 1;
    const int gid = lane >> 2, tig = lane & 3;
    const int lrow = lane & 7, lgrp = lane >> 3;
    const int arow = wm * 16 + lrow + ((lgrp & 1) ? 8 : 0);
    const int acol = (lgrp & 2) ? 8 : 0;
    const int brow = wn * 32 + lrow + ((lgrp >> 1) ? 8 : 0);
    const int bcol = (lgrp & 1) ? 8 : 0;
    float acc[4][4] = {};

    const int T = NSEQ / 2;   // 128
    LG_LOAD(0, 0);
    LG_LOAD(1, 1);
    int st = 0, ld = 2;
    for (int t = 0; t < T; t++) {
        if (t + 1 < T) { CP_WAIT(1); } else { CP_WAIT(0); }
        __syncthreads();
        if (t + 2 < T) {
            LG_LOAD(ld, t + 2);
            ld = (ld == 2) ? 0 : ld + 1;
        }
        #pragma unroll
        for (int ks = 0; ks < 4; ks++) {
            const int kb = ks * 16;
            uint32_t a[4], bfr[4][2];
            ldsm_x4(a[0], a[1], a[2], a[3], &As[st][arow][kb + acol]);
            #pragma unroll
            for (int p = 0; p < 2; p++)
                ldsm_x4(bfr[2*p][0], bfr[2*p][1], bfr[2*p+1][0], bfr[2*p+1][1],
                        &Bs[st][brow + p * 16][kb + bcol]);
            #pragma unroll
            for (int nt = 0; nt < 4; nt++)
                mma_f16(acc[nt], a[0], a[1], a[2], a[3], bfr[nt][0], bfr[nt][1]);
        }
        st = (st == 2) ? 0 : st + 1;
    }
    const size_t ob = (size_t)h * LRES * LRES;
    const int r0 = i0 + wm * 16 + gid;
    #pragma unroll
    for (int nt = 0; nt < 4; nt++) {
        const int col = j0 + wn * 32 + nt * 8 + 2 * tig;
        *(float2*)(out + ob + (size_t)r0 * LRES + col)     = make_float2(acc[nt][0], acc[nt][1]);
        *(float2*)(out + ob + (size_t)(r0+8) * LRES + col) = make_float2(acc[nt][2], acc[nt][3]);
    }
}
#undef LG_LOAD

// =========================================================================
// K6: fused pair-bias + softmax -> fp16 attn. One block per i (256 thr).
// =========================================================================
__global__ void __launch_bounds__(256) pairsoftmax_kernel(
    const float* __restrict__ pair, const float* __restrict__ g,
    const float* __restrict__ b, const float* __restrict__ Wb,
    const float* __restrict__ logits, __half* __restrict__ attn)
{
    __shared__ float bias_s[LRES][NH + 1];
    const int i = blockIdx.x;
    const int w = threadIdx.x >> 5, lane = threadIdx.x & 31;

    for (int j = w; j < LRES; j += 8) {
        const size_t p = (size_t)i * LRES + j;
        float4 v = *(const float4*)(pair + p * DP + lane * 4);
        float s  = v.x + v.y + v.z + v.w;
        float s2 = v.x*v.x + v.y*v.y + v.z*v.z + v.w*v.w;
        #pragma unroll
        for (int o = 16; o; o >>= 1) {
            s  += __shfl_xor_sync(0xffffffffu, s,  o);
            s2 += __shfl_xor_sync(0xffffffffu, s2, o);
        }
        const float mu   = s * (1.f / DP);
        const float rstd = rsqrtf(s2 * (1.f / DP) - mu * mu + EPS);
        float xv[4] = {v.x, v.y, v.z, v.w};
        float acc[8] = {};
        #pragma unroll
        for (int c = 0; c < 4; c++) {
            const int d = lane * 4 + c;
            const float y = (xv[c] - mu) * rstd * g[d] + b[d];
            const float* wr = Wb + d * NH;
            #pragma unroll
            for (int hh = 0; hh < 8; hh++) acc[hh] = fmaf(y, wr[hh], acc[hh]);
        }
        #pragma unroll
        for (int hh = 0; hh < 8; hh++) {
            float a = acc[hh];
            #pragma unroll
            for (int o = 16; o; o >>= 1) a += __shfl_xor_sync(0xffffffffu, a, o);
            if (lane == hh) bias_s[j][hh] = a;
        }
    }
    __syncthreads();

    const int h = w;
    const size_t base = ((size_t)h * LRES + i) * LRES;
    float x[12];
    #pragma unroll
    for (int r = 0; r < 6; r++) {
        const int j = 2 * lane + 64 * r;
        float2 lg = *(const float2*)(logits + base + j);
        x[2*r]   = lg.x + bias_s[j][h];
        x[2*r+1] = lg.y + bias_s[j + 1][h];
    }
    float mx = x[0];
    #pragma unroll
    for (int r = 1; r < 12; r++) mx = fmaxf(mx, x[r]);
    #pragma unroll
    for (int o = 16; o; o >>= 1) mx = fmaxf(mx, __shfl_xor_sync(0xffffffffu, mx, o));
    float e[12], sum = 0.f;
    #pragma unroll
    for (int r = 0; r < 12; r++) { e[r] = expf(x[r] - mx); sum += e[r]; }
    #pragma unroll
    for (int o = 16; o; o >>= 1) sum += __shfl_xor_sync(0xffffffffu, sum, o);
    const float inv = 1.f / sum;
    #pragma unroll
    for (int r = 0; r < 6; r++) {
        *(uint32_t*)(attn + base + 2 * lane + 64 * r) =
            f2h2(e[2*r] * inv, e[2*r+1] * inv);
    }
}

// =========================================================================
// T3: aog = fp16(gate * (attn @ v)). Block 128(i) x 64(nd), BK=32(j).
// B = v[n,j,h,d] loaded as [j][nd] smem tiles, ldmatrix.trans fragments.
// grid (3, 128, 8).
// =========================================================================
#define AO_LOAD(stg, j0) do {                                                       \
    _Pragma("unroll")                                                               \
    for (int s_ = 0; s_ < 2; s_++) {                                                \
        const int r_ = (tid >> 2) + 64 * s_;                                        \
        const int c_ = (tid & 3) * 8;                                               \
        cp16(&As[stg][r_][c_], Ah + (size_t)(i0 + r_) * LRES + (j0) + c_);          \
    }                                                                               \
    {                                                                               \
        const int jj_ = tid >> 3;        /* 0..31 j within tile */                  \
        const int cc_ = (tid & 7) * 8;   /* 0..56 nd chunk */                       \
        const int nB_ = (blockIdx.y << 1) + (cc_ >> 5);                             \
        const int dB_ = cc_ & 31;                                                   \
        cp16(&Bs[stg][jj_][cc_],                                                    \
             vv + ((size_t)nB_ * LRES + (j0) + jj_) * HD + h * DHD + dB_);          \
    }                                                                               \
    CP_COMMIT();                                                                    \
} while (0)

__global__ void __launch_bounds__(256, 2) attnout_tc_kernel(
    const __half* __restrict__ attn, const __half* __restrict__ vv,
    const __half* __restrict__ gate, __half* __restrict__ aog)
{
    __shared__ __half As[3][128][40];
    __shared__ __half Bs[3][32][72];   // [j][nd]
    const int tid = threadIdx.x;
    const int i0 = blockIdx.x * 128;
    const int h  = blockIdx.z;
    const int lane = tid & 31, w = tid >> 5;
    const int wm = w >> 1, wn = w & 1;
    const int gid = lane >> 2, tig = lane & 3;
    const int lrow = lane & 7, lgrp = lane >> 3;
    const int arow = wm * 32 + lrow + ((lgrp & 1) ? 8 : 0);
    const int acol = (lgrp & 2) ? 8 : 0;
    const int btrow = lrow + ((lgrp & 1) ? 8 : 0);
    const int btcol = wn * 32 + ((lgrp >> 1) ? 8 : 0);
    const __half* Ah = attn + (size_t)h * LRES * LRES;
    float acc[2][4][4] = {};

    const int T = LRES / 32;  // 12
    AO_LOAD(0, 0);
    AO_LOAD(1, 32);
    int st = 0, ld = 2;
    for (int t = 0; t < T; t++) {
        if (t + 1 < T) { CP_WAIT(1); } else { CP_WAIT(0); }
        __syncthreads();
        if (t + 2 < T) {
            AO_LOAD(ld, (t + 2) * 32);
            ld = (ld == 2) ? 0 : ld + 1;
        }
        #pragma unroll
        for (int ks = 0; ks < 2; ks++) {
            const int kb = ks * 16;
            uint32_t a[2][4], bfr[4][2];
            #pragma unroll
            for (int mt = 0; mt < 2; mt++)
                ldsm_x4(a[mt][0], a[mt][1], a[mt][2], a[mt][3],
                        &As[st][arow + mt * 16][kb + acol]);
            #pragma unroll
            for (int p = 0; p < 2; p++)
                ldsm_x4t(bfr[2*p][0], bfr[2*p][1], bfr[2*p+1][0], bfr[2*p+1][1],
                         &Bs[st][kb + btrow][btcol + p * 16]);
            #pragma unroll
            for (int mt = 0; mt < 2; mt++)
                #pragma unroll
                for (int nt = 0; nt < 4; nt++)
                    mma_f16(acc[mt][nt], a[mt][0], a[mt][1], a[mt][2], a[mt][3],
                            bfr[nt][0], bfr[nt][1]);
        }
        st = (st == 2) ? 0 : st + 1;
    }
    #pragma unroll
    for (int mt = 0; mt < 2; mt++) {
        const int r0 = i0 + wm * 32 + mt * 16 + gid;
        #pragma unroll
        for (int nt = 0; nt < 4; nt++) {
            const int col = wn * 32 + nt * 8 + 2 * tig;      // nd within 64
            const int nOut = (blockIdx.y << 1) + (col >> 5);
            const int d = col & 31;
            const size_t p0 = ((size_t)nOut * LRES + r0) * HD + h * DHD + d;
            const size_t p1 = ((size_t)nOut * LRES + r0 + 8) * HD + h * DHD + d;
            const float2 gA = __half22float2(*(const __half2*)(gate + p0));
            const float2 gB = __half22float2(*(const __half2*)(gate + p1));
            *(uint32_t*)(aog + p0) = f2h2(acc[mt][nt][0] * gA.x, acc[mt][nt][1] * gA.y);
            *(uint32_t*)(aog + p1) = f2h2(acc[mt][nt][2] * gB.x, acc[mt][nt][3] * gB.y);
        }
    }
}
#undef AO_LOAD

// =========================================================================
// launcher
// =========================================================================
extern "C" void kernel_launch(void* const* d_in, const int* in_sizes, int n_in,
                              void* d_out, int out_size)
{
    const float* msa       = (const float*)d_in[0];
    const float* pair      = (const float*)d_in[1];
    const float* ln_msa_g  = (const float*)d_in[2];
    const float* ln_msa_b  = (const float*)d_in[3];
    const float* ln_pair_g = (const float*)d_in[4];
    const float* ln_pair_b = (const float*)d_in[5];
    const float* Wq_sw     = (const float*)d_in[6];
    const float* bq_sw     = (const float*)d_in[7];
    const float* Wk_sw     = (const float*)d_in[8];
    const float* bk_sw     = (const float*)d_in[9];   // unused: cancels in softmax
    const float* Wq        = (const float*)d_in[10];
    const float* Wk        = (const float*)d_in[11];
    const float* Wv        = (const float*)d_in[12];
    const float* Wb        = (const float*)d_in[13];
    const float* Wg        = (const float*)d_in[14];
    const float* bg        = (const float*)d_in[15];
    const float* Wo        = (const float*)d_in[16];
    const float* bo        = (const float*)d_in[17];
    float* out = (float*)d_out;
    (void)bk_sw;

    __half *m_, *t_, *qw_, *k_, *v_, *gate_, *aog_, *attn_, *wpackT_, *w2T_;
    float *qsw_, *sw_, *logits_;
    cudaGetSymbolAddress((void**)&m_,      g_m);
    cudaGetSymbolAddress((void**)&qsw_,    g_qsw);
    cudaGetSymbolAddress((void**)&t_,      g_t);
    cudaGetSymbolAddress((void**)&qw_,     g_qw);
    cudaGetSymbolAddress((void**)&k_,      g_k);
    cudaGetSymbolAddress((void**)&v_,      g_v);
    cudaGetSymbolAddress((void**)&gate_,   g_gate);
    cudaGetSymbolAddress((void**)&aog_,    g_aog);
    cudaGetSymbolAddress((void**)&sw_,     g_sw);
    cudaGetSymbolAddress((void**)&logits_, g_logits);
    cudaGetSymbolAddress((void**)&attn_,   g_attn);
    cudaGetSymbolAddress((void**)&wpackT_, g_wpackT);
    cudaGetSymbolAddress((void**)&w2T_,    g_w2T);

    const float scale = 0.17677669529663687f;  // 1/sqrt(32)
    const __half *WqSWT = w2T_, *WOT = w2T_ + DM * DM;

    const int LG_SMEM = (3 * 64 * 72 * 2) * 2;    // 55296
    cudaFuncSetAttribute((const void*)logits_tc_kernel,
        cudaFuncAttributeMaxDynamicSharedMemorySize, LG_SMEM);

    // preprocessing: pack transposed fp16 weights (Q|K|V|G), LN
    cvt_pack_kernel<<<(DM * NWIDE) / 256, 256>>>(Wq, Wk, Wv, Wg, wpackT_);
    cvt2_kernel<<<dim3(DM * DM / 256, 2), 256>>>(Wq_sw, Wo, w2T_);
    ln_msa_kernel<<<NLROWS / 8, 256>>>(msa, ln_msa_g, ln_msa_b, m_);

    // qsw: (m0 @ Wq_sw + bq_sw) * scale (fp32 out)
    wgemm_kernel<1><<<dim3(HD / 64, LRES / 128), 256>>>(
        m_, WqSWT, LRES, DM, HD,
        nullptr, nullptr, nullptr, nullptr, nullptr, bq_sw, nullptr, scale, qsw_);

    // t vectors + seq weights (needed by projection epilogue)
    t_kernel<<<dim3(LRES, NH), 256>>>(qsw_, Wk_sw, t_);
    seqw2_kernel<<<LRES, 256>>>(m_, t_, sw_);

    // fused 4-way projection; q segment scaled by sw -> qw directly
    wgemm_kernel<0><<<dim3(NWIDE / 64, NLROWS / 128), 256>>>(
        m_, wpackT_, NLROWS, DM, NWIDE,
        qw_, k_, v_, gate_, sw_, nullptr, bg, scale, nullptr);

    // logits
    logits_tc_kernel<<<dim3(LRES / 64, LRES / 64, NH), 256, LG_SMEM>>>(qw_, k_, logits_);

    // fused pair bias + softmax (fp16 attn)
    pairsoftmax_kernel<<<LRES, 256>>>(pair, ln_pair_g, ln_pair_b, Wb, logits_, attn_);

    // attn @ v (gate fused, v read directly via ldmatrix.trans)
    attnout_tc_kernel<<<dim3(LRES / 128, NSEQ / 2, NH), 256>>>(attn_, v_, gate_, aog_);

    // final: aog @ Wo + bo
    wgemm_kernel<1><<<dim3(DM / 64, NLROWS / 128), 256>>>(
        aog_, WOT, NLROWS, DM, DM,
        nullptr, nullptr, nullptr, nullptr, nullptr, bo, nullptr, 1.f, out);
}